// round 14
// baseline (speedup 1.0000x reference)
#include <cuda_runtime.h>
#include <cuda_fp16.h>
#include <mma.h>
#include <cstdint>
#include <cstddef>
using namespace nvcuda;

#define DI __device__ __forceinline__

constexpr int D = 1024, F = 4096, E = 8, T = 8192;
constexpr int BM = 128, BN = 128, BK = 64;
constexpr int NST = 2;
constexpr int NTHR = 128;                  // 4 warps, 64x64 warp tiles (2x2)
constexpr int ROWS_PAD = 2 * T + E * BM;   // 17408
constexpr int MAXMT = ROWS_PAD / BM;       // 136
constexpr int LDA_S = BK + 8;              // 72 halfs
constexpr int LDB_S = BN + 8;              // 136 halfs
constexpr int A_ELE = BM * LDA_S;          // 9216 halfs / stage
constexpr int B_ELE = BK * LDB_S;          // 8704 halfs / stage
constexpr int SMEM_DYN = NST * (A_ELE + B_ELE) * 2;  // 71680 B (2 CTAs/SM, L1 ~85KB)

// ---- static device scratch (no allocations) ----
__device__ __half g_xh [(size_t)T * D];        // x fp16, token order
__device__ __half g_W1h[(size_t)E * D * F];
__device__ __half g_W2h[(size_t)E * F * D];
__device__ __half g_H  [(size_t)ROWS_PAD * F];
__device__ float  g_O  [(size_t)ROWS_PAD * D];
__device__ int   g_cnt[E], g_fill[E], g_off[E];
__device__ int   g_texp[2 * T];
__device__ float g_twt [2 * T];
__device__ int   g_pos [2 * T];
__device__ int   g_rows[ROWS_PAD];
__device__ int   g_tile_e[MAXMT], g_tile_r0[MAXMT];
__device__ int   g_nmt;

DI void cpa16_cg(void* dst, const void* src) {     // L1-bypass
    uint32_t d = (uint32_t)__cvta_generic_to_shared(dst);
    asm volatile("cp.async.cg.shared.global [%0], [%1], 16;"
                 :: "r"(d), "l"(__cvta_generic_to_global(src)) : "memory");
}
DI void cpa16_ca(void* dst, const void* src) {     // L1-allocating (cross-CTA sharing)
    uint32_t d = (uint32_t)__cvta_generic_to_shared(dst);
    asm volatile("cp.async.ca.shared.global [%0], [%1], 16;"
                 :: "r"(d), "l"(__cvta_generic_to_global(src)) : "memory");
}
#define CP_COMMIT asm volatile("cp.async.commit_group;" ::: "memory")
#define CP_WAIT(n) asm volatile("cp.async.wait_group %0;" :: "n"(n) : "memory")

// ---- gating: one warp per token, float4 loads ----
__global__ void k_zero() { if (threadIdx.x < E) { g_cnt[threadIdx.x] = 0; g_fill[threadIdx.x] = 0; } }

__global__ void k_gate(const float* __restrict__ x, const float* __restrict__ Wg,
                       const float* __restrict__ bg) {
    int warp = threadIdx.x >> 5, lane = threadIdx.x & 31;
    int t = blockIdx.x * 8 + warp;
    if (t >= T) return;
    float acc[E];
#pragma unroll
    for (int e = 0; e < E; e++) acc[e] = 0.f;
    const float* xr = x + (size_t)t * D;
#pragma unroll
    for (int it = 0; it < D / 128; it++) {
        int d = (it * 32 + lane) * 4;
        float4 xv = *(const float4*)(xr + d);
        const float* xs = &xv.x;
#pragma unroll
        for (int s = 0; s < 4; s++) {
            const float4* w = (const float4*)(Wg + (size_t)(d + s) * E);
            float4 w0 = w[0], w1 = w[1];
            float xvs = xs[s];
            acc[0] += xvs * w0.x; acc[1] += xvs * w0.y; acc[2] += xvs * w0.z; acc[3] += xvs * w0.w;
            acc[4] += xvs * w1.x; acc[5] += xvs * w1.y; acc[6] += xvs * w1.z; acc[7] += xvs * w1.w;
        }
    }
#pragma unroll
    for (int e = 0; e < E; e++)
#pragma unroll
        for (int o = 16; o > 0; o >>= 1) acc[e] += __shfl_down_sync(0xffffffffu, acc[e], o);
    if (lane == 0) {
        float l[E], m = -1e30f;
#pragma unroll
        for (int e = 0; e < E; e++) { l[e] = acc[e] + bg[e]; m = fmaxf(m, l[e]); }
        float p[E], s = 0.f;
#pragma unroll
        for (int e = 0; e < E; e++) { p[e] = __expf(l[e] - m); s += p[e]; }
        float inv = 1.f / s;
#pragma unroll
        for (int e = 0; e < E; e++) p[e] *= inv;
        int e0 = 0;
#pragma unroll
        for (int e = 1; e < E; e++) if (p[e] > p[e0]) e0 = e;
        int e1 = (e0 == 0) ? 1 : 0;
#pragma unroll
        for (int e = 0; e < E; e++) if (e != e0 && p[e] > p[e1]) e1 = e;
        g_texp[2 * t] = e0;     g_twt[2 * t] = p[e0];
        g_texp[2 * t + 1] = e1; g_twt[2 * t + 1] = p[e1];
        atomicAdd(&g_cnt[e0], 1); atomicAdd(&g_cnt[e1], 1);
    }
}

__global__ void k_sched() {
    if (threadIdx.x == 0) {
        int off = 0, nt = 0;
        for (int e = 0; e < E; e++) {
            g_off[e] = off;
            int c = g_cnt[e], ntile = (c + BM - 1) / BM;
            for (int i = 0; i < ntile; i++) { g_tile_e[nt] = e; g_tile_r0[nt] = off + i * BM; nt++; }
            off += ntile * BM;
        }
        g_nmt = nt;
    }
}

__global__ void k_scatter() {
    int t = blockIdx.x * blockDim.x + threadIdx.x;
    if (t >= T) return;
#pragma unroll
    for (int k = 0; k < 2; k++) {
        int e = g_texp[2 * t + k];
        int p = atomicAdd(&g_fill[e], 1);
        int row = g_off[e] + p;
        g_pos[2 * t + k] = row;
        g_rows[row] = t;
    }
}

__global__ void k_convW(const float* __restrict__ src, __half* __restrict__ dst, size_t n8) {
    size_t idx = (size_t)blockIdx.x * blockDim.x + threadIdx.x;
    if (idx >= n8) return;
    const float4* s = (const float4*)(src + idx * 8);
    float4 a = s[0], b = s[1];
    __half h[8];
    h[0] = __float2half(a.x); h[1] = __float2half(a.y); h[2] = __float2half(a.z); h[3] = __float2half(a.w);
    h[4] = __float2half(b.x); h[5] = __float2half(b.y); h[6] = __float2half(b.z); h[7] = __float2half(b.w);
    *(uint4*)(dst + idx * 8) = *(uint4*)h;
}

// ---- tiled wmma GEMM: 128x128 CTA, 4 warps @ 64x64, NST=2, 2 CTAs/SM ----
// nfast=0: grid x=M-tile (fast), .ca on B (co-resident CTAs share B).  [GEMM1]
// nfast=1: grid x=N-tile (fast), .ca on A (co-resident CTAs share A; H L2-reuse). [GEMM2]
__global__ __launch_bounds__(NTHR, 2) void k_gemm(
    const __half* __restrict__ A, const __half* __restrict__ Bw,
    const float* __restrict__ bias, void* __restrict__ Out,
    int K, int N, int relu_half, const int* __restrict__ rmap, int nfast)
{
    int mt = nfast ? blockIdx.y : blockIdx.x;
    int bn = nfast ? blockIdx.x : blockIdx.y;
    if (mt >= g_nmt) return;
    int e = g_tile_e[mt], row0 = g_tile_r0[mt];
    const __half* Be = Bw + (size_t)e * K * N;
    const float* bp_e = bias + (size_t)e * N;

    extern __shared__ __align__(16) __half smem[];
    __half* smA = smem;
    __half* smB = smem + NST * A_ELE;
    __shared__ int srows[BM];

    int tid = threadIdx.x, lane = tid & 31, warp = tid >> 5;
    int wm = warp >> 1, wn = warp & 1;        // 2x2 warp grid, 64x64 each

    srows[tid] = rmap ? rmap[row0 + tid] : (row0 + tid);
    __syncthreads();

    wmma::fragment<wmma::accumulator, 16, 16, 16, float> c[4][4];
#pragma unroll
    for (int i = 0; i < 4; i++)
#pragma unroll
        for (int j = 0; j < 4; j++) wmma::fill_fragment(c[i][j], 0.f);

    auto load_tiles = [&](int buf, int k0) {
        __half* dA = smA + buf * A_ELE;
        __half* dB = smB + buf * B_ELE;
        if (nfast) {
#pragma unroll
            for (int i = 0; i < 8; i++) {          // A shared by co-resident CTAs -> .ca
                int q = i * NTHR + tid;
                int r = q >> 3, ch = q & 7;
                cpa16_ca(dA + r * LDA_S + ch * 8, A + (size_t)srows[r] * K + k0 + ch * 8);
            }
#pragma unroll
            for (int i = 0; i < 8; i++) {
                int q = i * NTHR + tid;
                int r = q >> 4, ch = q & 15;
                cpa16_cg(dB + r * LDB_S + ch * 8, Be + (size_t)(k0 + r) * N + bn * BN + ch * 8);
            }
        } else {
#pragma unroll
            for (int i = 0; i < 8; i++) {
                int q = i * NTHR + tid;
                int r = q >> 3, ch = q & 7;
                cpa16_cg(dA + r * LDA_S + ch * 8, A + (size_t)srows[r] * K + k0 + ch * 8);
            }
#pragma unroll
            for (int i = 0; i < 8; i++) {          // B shared by co-resident CTAs -> .ca
                int q = i * NTHR + tid;
                int r = q >> 4, ch = q & 15;
                cpa16_ca(dB + r * LDB_S + ch * 8, Be + (size_t)(k0 + r) * N + bn * BN + ch * 8);
            }
        }
    };

    int ktiles = K / BK;
    load_tiles(0, 0); CP_COMMIT;

    wmma::fragment<wmma::matrix_a, 16, 16, 16, half, wmma::row_major> a[2][4];
    wmma::fragment<wmma::matrix_b, 16, 16, 16, half, wmma::row_major> b[2][4];

    for (int kt = 0; kt < ktiles; kt++) {
        CP_WAIT(0);        // stage kt resident (loaded during compute of kt-1)
        __syncthreads();   // all warps done with buf (kt+1)&1 from compute kt-1
        if (kt + 1 < ktiles) { load_tiles((kt + 1) & 1, (kt + 1) * BK); CP_COMMIT; }

        const __half* Ab = smA + (kt & 1) * A_ELE;
        const __half* Bb = smB + (kt & 1) * B_ELE;

        // preload kk=0 fragments into slot 0
#pragma unroll
        for (int i = 0; i < 4; i++)
            wmma::load_matrix_sync(a[0][i], Ab + (wm * 64 + i * 16) * LDA_S, LDA_S);
#pragma unroll
        for (int j = 0; j < 4; j++)
            wmma::load_matrix_sync(b[0][j], Bb + wn * 64 + j * 16, LDB_S);

#pragma unroll
        for (int kk = 0; kk < 4; kk++) {
            int cur = kk & 1, nxt = cur ^ 1;
            if (kk < 3) {   // issue next-kk fragment loads ahead of this kk's MMAs
#pragma unroll
                for (int i = 0; i < 4; i++)
                    wmma::load_matrix_sync(a[nxt][i], Ab + (wm * 64 + i * 16) * LDA_S + (kk + 1) * 16, LDA_S);
#pragma unroll
                for (int j = 0; j < 4; j++)
                    wmma::load_matrix_sync(b[nxt][j], Bb + (kk + 1) * 16 * LDB_S + wn * 64 + j * 16, LDB_S);
            }
#pragma unroll
            for (int i = 0; i < 4; i++)
#pragma unroll
                for (int j = 0; j < 4; j++)
                    wmma::mma_sync(c[i][j], a[cur][i], b[cur][j], c[i][j]);
        }
    }

    if (!relu_half) {
        // direct fp32 store, no bias (bias folded into combine)
#pragma unroll
        for (int i = 0; i < 4; i++)
#pragma unroll
            for (int j = 0; j < 4; j++) {
                float* o = (float*)Out + (size_t)(row0 + wm * 64 + i * 16) * N
                         + bn * BN + wn * 64 + j * 16;
                wmma::store_matrix_sync(o, c[i][j], N, wmma::mem_row_major);
            }
        return;
    }

    __syncthreads();   // protect smA before epilogue staging reuse
    float* cst = reinterpret_cast<float*>(smA) + warp * 256;
    int lr = lane >> 1, lc = (lane & 1) * 8;
#pragma unroll
    for (int i = 0; i < 4; i++)
#pragma unroll
        for (int j = 0; j < 4; j++) {
            wmma::store_matrix_sync(cst, c[i][j], 16, wmma::mem_row_major);
            __syncwarp();
            int gr = row0 + wm * 64 + i * 16 + lr;
            int gc = bn * BN + wn * 64 + j * 16 + lc;
            const float* srcp = cst + lr * 16 + lc;
            __half h[8];
#pragma unroll
            for (int u = 0; u < 8; u++) {
                float v = srcp[u] + bp_e[gc + u];
                h[u] = __float2half(v > 0.f ? v : 0.f);
            }
            *(uint4*)((__half*)Out + (size_t)gr * N + gc) = *(uint4*)h;
            __syncwarp();
        }
}

__global__ void k_combine(const float* __restrict__ b2, float* __restrict__ out) {
    int idx = blockIdx.x * blockDim.x + threadIdx.x;
    const int CW = D / 4;
    if (idx >= T * CW) return;
    int t = idx / CW, c4 = (idx % CW) * 4;
    int p0 = g_pos[2 * t], p1 = g_pos[2 * t + 1];
    int e0 = g_texp[2 * t], e1 = g_texp[2 * t + 1];
    float w0 = g_twt[2 * t], w1 = g_twt[2 * t + 1];
    float4 a = *(const float4*)(g_O + (size_t)p0 * D + c4);
    float4 b = *(const float4*)(g_O + (size_t)p1 * D + c4);
    float4 ba = *(const float4*)(b2 + (size_t)e0 * D + c4);
    float4 bb = *(const float4*)(b2 + (size_t)e1 * D + c4);
    float4 r;
    r.x = w0 * (a.x + ba.x) + w1 * (b.x + bb.x);
    r.y = w0 * (a.y + ba.y) + w1 * (b.y + bb.y);
    r.z = w0 * (a.z + ba.z) + w1 * (b.z + bb.z);
    r.w = w0 * (a.w + ba.w) + w1 * (b.w + bb.w);
    *(float4*)(out + (size_t)t * D + c4) = r;
}

extern "C" void kernel_launch(void* const* d_in, const int* in_sizes, int n_in,
                              void* d_out, int out_size) {
    const float* x  = (const float*)d_in[0];
    const float* Wg = (const float*)d_in[1];
    const float* bg = (const float*)d_in[2];
    const float* W1 = (const float*)d_in[3];
    const float* b1 = (const float*)d_in[4];
    const float* W2 = (const float*)d_in[5];
    const float* b2 = (const float*)d_in[6];
    float* out = (float*)d_out;

    __half *w1h, *w2h, *xh, *Hh; float* Oo; int* rowsp;
    cudaGetSymbolAddress((void**)&w1h, g_W1h);
    cudaGetSymbolAddress((void**)&w2h, g_W2h);
    cudaGetSymbolAddress((void**)&xh, g_xh);
    cudaGetSymbolAddress((void**)&Hh, g_H);
    cudaGetSymbolAddress((void**)&Oo, g_O);
    cudaGetSymbolAddress((void**)&rowsp, g_rows);

    cudaFuncSetAttribute(k_gemm, cudaFuncAttributeMaxDynamicSharedMemorySize, SMEM_DYN);
    cudaFuncSetAttribute(k_gemm, cudaFuncAttributePreferredSharedMemoryCarveout, 63);

    k_zero<<<1, 32>>>();
    k_gate<<<T / 8, 256>>>(x, Wg, bg);
    k_sched<<<1, 32>>>();
    k_scatter<<<T / 256, 256>>>();
    size_t nX = (size_t)T * D / 8;
    k_convW<<<(unsigned)((nX + 255) / 256), 256>>>(x, xh, nX);
    size_t nW = (size_t)E * D * F / 8;
    k_convW<<<(unsigned)((nW + 255) / 256), 256>>>(W1, w1h, nW);
    k_convW<<<(unsigned)((nW + 255) / 256), 256>>>(W2, w2h, nW);
    // GEMM1: H = relu(x[rows] @ W1[e] + b1[e])   [K=D, N=F], x=M-fast, .ca B
    k_gemm<<<dim3(MAXMT, F / BN), NTHR, SMEM_DYN>>>(xh, w1h, b1, (void*)Hh, D, F, 1, rowsp, 0);
    // GEMM2: O = H @ W2[e]                        [K=F, N=D], x=N-fast (H L2-reuse), .ca A
    k_gemm<<<dim3(D / BN, MAXMT), NTHR, SMEM_DYN>>>(Hh, w2h, b2, (void*)Oo, F, D, 0, nullptr, 1);
    k_combine<<<(T * (D / 4) + 255) / 256, 256>>>(b2, out);
}

// round 15
// speedup vs baseline: 1.0432x; 1.0432x over previous
#include <cuda_runtime.h>
#include <cuda_fp16.h>
#include <mma.h>
#include <cstdint>
#include <cstddef>
using namespace nvcuda;

#define DI __device__ __forceinline__

constexpr int D = 1024, F = 4096, E = 8, T = 8192;
constexpr int BM = 128, BN = 128, BK = 64;
constexpr int NST = 2;
constexpr int NTHR = 128;                  // 4 warps, 64x64 warp tiles (2x2)
constexpr int ROWS_PAD = 2 * T + E * BM;   // 17408
constexpr int MAXMT = ROWS_PAD / BM;       // 136
constexpr int LDA_S = BK + 8;              // 72 halfs
constexpr int LDB_S = BN + 8;              // 136 halfs
constexpr int A_ELE = BM * LDA_S;          // 9216 halfs / stage
constexpr int B_ELE = BK * LDB_S;          // 8704 halfs / stage
constexpr int SMEM_DYN = NST * (A_ELE + B_ELE) * 2;  // 71680 B (2 CTAs/SM, L1 ~85KB)

// ---- static device scratch (no allocations) ----
__device__ __half g_xh [(size_t)T * D];        // x fp16, token order
__device__ __half g_W1h[(size_t)E * D * F];
__device__ __half g_W2h[(size_t)E * F * D];
__device__ __half g_H  [(size_t)ROWS_PAD * F];
__device__ float  g_O  [(size_t)ROWS_PAD * D];
__device__ int   g_cnt[E], g_fill[E], g_off[E];
__device__ int   g_texp[2 * T];
__device__ float g_twt [2 * T];
__device__ int   g_pos [2 * T];
__device__ int   g_rows[ROWS_PAD];
__device__ int   g_tile_e[MAXMT], g_tile_r0[MAXMT];
__device__ int   g_nmt;

DI void cpa16_cg(void* dst, const void* src) {     // L1-bypass (A: no cross-CTA reuse)
    uint32_t d = (uint32_t)__cvta_generic_to_shared(dst);
    asm volatile("cp.async.cg.shared.global [%0], [%1], 16;"
                 :: "r"(d), "l"(__cvta_generic_to_global(src)) : "memory");
}
DI void cpa16_ca(void* dst, const void* src) {     // L1-allocating (B: shared by co-resident CTAs)
    uint32_t d = (uint32_t)__cvta_generic_to_shared(dst);
    asm volatile("cp.async.ca.shared.global [%0], [%1], 16;"
                 :: "r"(d), "l"(__cvta_generic_to_global(src)) : "memory");
}
#define CP_COMMIT asm volatile("cp.async.commit_group;" ::: "memory")
#define CP_WAIT(n) asm volatile("cp.async.wait_group %0;" :: "n"(n) : "memory")

// ---- gating: one warp per token, float4 x loads ----
__global__ void k_zero() { if (threadIdx.x < E) { g_cnt[threadIdx.x] = 0; g_fill[threadIdx.x] = 0; } }

__global__ void k_gate(const float* __restrict__ x, const float* __restrict__ Wg,
                       const float* __restrict__ bg) {
    int warp = threadIdx.x >> 5, lane = threadIdx.x & 31;
    int t = blockIdx.x * 8 + warp;
    if (t >= T) return;
    float acc[E];
#pragma unroll
    for (int e = 0; e < E; e++) acc[e] = 0.f;
    const float* xr = x + (size_t)t * D;
#pragma unroll
    for (int it = 0; it < D / 128; it++) {
        int d = (it * 32 + lane) * 4;
        float4 xv = *(const float4*)(xr + d);
        const float* xs = &xv.x;
#pragma unroll
        for (int s = 0; s < 4; s++) {
            const float4* w = (const float4*)(Wg + (size_t)(d + s) * E);
            float4 w0 = w[0], w1 = w[1];
            float xvs = xs[s];
            acc[0] += xvs * w0.x; acc[1] += xvs * w0.y; acc[2] += xvs * w0.z; acc[3] += xvs * w0.w;
            acc[4] += xvs * w1.x; acc[5] += xvs * w1.y; acc[6] += xvs * w1.z; acc[7] += xvs * w1.w;
        }
    }
#pragma unroll
    for (int e = 0; e < E; e++)
#pragma unroll
        for (int o = 16; o > 0; o >>= 1) acc[e] += __shfl_down_sync(0xffffffffu, acc[e], o);
    if (lane == 0) {
        float l[E], m = -1e30f;
#pragma unroll
        for (int e = 0; e < E; e++) { l[e] = acc[e] + bg[e]; m = fmaxf(m, l[e]); }
        float p[E], s = 0.f;
#pragma unroll
        for (int e = 0; e < E; e++) { p[e] = __expf(l[e] - m); s += p[e]; }
        float inv = 1.f / s;
#pragma unroll
        for (int e = 0; e < E; e++) p[e] *= inv;
        int e0 = 0;
#pragma unroll
        for (int e = 1; e < E; e++) if (p[e] > p[e0]) e0 = e;
        int e1 = (e0 == 0) ? 1 : 0;
#pragma unroll
        for (int e = 0; e < E; e++) if (e != e0 && p[e] > p[e1]) e1 = e;
        g_texp[2 * t] = e0;     g_twt[2 * t] = p[e0];
        g_texp[2 * t + 1] = e1; g_twt[2 * t + 1] = p[e1];
        atomicAdd(&g_cnt[e0], 1); atomicAdd(&g_cnt[e1], 1);
    }
}

__global__ void k_sched() {
    if (threadIdx.x == 0) {
        int off = 0, nt = 0;
        for (int e = 0; e < E; e++) {
            g_off[e] = off;
            int c = g_cnt[e], ntile = (c + BM - 1) / BM;
            for (int i = 0; i < ntile; i++) { g_tile_e[nt] = e; g_tile_r0[nt] = off + i * BM; nt++; }
            off += ntile * BM;
        }
        g_nmt = nt;
    }
}

__global__ void k_scatter() {
    int t = blockIdx.x * blockDim.x + threadIdx.x;
    if (t >= T) return;
#pragma unroll
    for (int k = 0; k < 2; k++) {
        int e = g_texp[2 * t + k];
        int p = atomicAdd(&g_fill[e], 1);
        int row = g_off[e] + p;
        g_pos[2 * t + k] = row;
        g_rows[row] = t;
    }
}

__global__ void k_convW(const float* __restrict__ src, __half* __restrict__ dst, size_t n8) {
    size_t idx = (size_t)blockIdx.x * blockDim.x + threadIdx.x;
    if (idx >= n8) return;
    const float4* s = (const float4*)(src + idx * 8);
    float4 a = s[0], b = s[1];
    __half h[8];
    h[0] = __float2half(a.x); h[1] = __float2half(a.y); h[2] = __float2half(a.z); h[3] = __float2half(a.w);
    h[4] = __float2half(b.x); h[5] = __float2half(b.y); h[6] = __float2half(b.z); h[7] = __float2half(b.w);
    *(uint4*)(dst + idx * 8) = *(uint4*)h;
}

// ---- tiled wmma GEMM: 128x128 CTA, 4 warps @ 64x64, NST=2, 2 CTAs/SM ----
// Grid x=M-fast; B via .ca (co-resident CTAs, adjacent M-tiles same bn, share B in L1).
__global__ __launch_bounds__(NTHR, 2) void k_gemm(
    const __half* __restrict__ A, const __half* __restrict__ Bw,
    const float* __restrict__ bias, void* __restrict__ Out,
    int K, int N, int relu_half, const int* __restrict__ rmap)
{
    if (blockIdx.x >= g_nmt) return;
    int e = g_tile_e[blockIdx.x], row0 = g_tile_r0[blockIdx.x];
    int bn = blockIdx.y;
    const __half* Be = Bw + (size_t)e * K * N;
    const float* bp_e = bias + (size_t)e * N;

    extern __shared__ __align__(16) __half smem[];
    __half* smA = smem;
    __half* smB = smem + NST * A_ELE;
    __shared__ int srows[BM];

    int tid = threadIdx.x, lane = tid & 31, warp = tid >> 5;
    int wm = warp >> 1, wn = warp & 1;        // 2x2 warp grid, 64x64 each

    srows[tid] = rmap ? rmap[row0 + tid] : (row0 + tid);
    __syncthreads();

    wmma::fragment<wmma::accumulator, 16, 16, 16, float> c[4][4];
#pragma unroll
    for (int i = 0; i < 4; i++)
#pragma unroll
        for (int j = 0; j < 4; j++) wmma::fill_fragment(c[i][j], 0.f);

    auto load_tiles = [&](int buf, int k0) {
        __half* dA = smA + buf * A_ELE;
        __half* dB = smB + buf * B_ELE;
#pragma unroll
        for (int i = 0; i < 8; i++) {              // A: 128 rows x 8 chunks of 16B
            int q = i * NTHR + tid;
            int r = q >> 3, ch = q & 7;
            cpa16_cg(dA + r * LDA_S + ch * 8, A + (size_t)srows[r] * K + k0 + ch * 8);
        }
#pragma unroll
        for (int i = 0; i < 8; i++) {              // B: 64 rows x 16 chunks of 16B
            int q = i * NTHR + tid;
            int r = q >> 4, ch = q & 15;
            cpa16_ca(dB + r * LDB_S + ch * 8, Be + (size_t)(k0 + r) * N + bn * BN + ch * 8);
        }
    };

    int ktiles = K / BK;
    load_tiles(0, 0); CP_COMMIT;

    wmma::fragment<wmma::matrix_a, 16, 16, 16, half, wmma::row_major> a[2][4];
    wmma::fragment<wmma::matrix_b, 16, 16, 16, half, wmma::row_major> b[2][4];

    for (int kt = 0; kt < ktiles; kt++) {
        CP_WAIT(0);        // stage kt resident (loaded during compute of kt-1)
        __syncthreads();   // all warps done with buf (kt+1)&1 from compute kt-1
        if (kt + 1 < ktiles) { load_tiles((kt + 1) & 1, (kt + 1) * BK); CP_COMMIT; }

        const __half* Ab = smA + (kt & 1) * A_ELE;
        const __half* Bb = smB + (kt & 1) * B_ELE;

        // preload kk=0 fragments into slot 0
#pragma unroll
        for (int i = 0; i < 4; i++)
            wmma::load_matrix_sync(a[0][i], Ab + (wm * 64 + i * 16) * LDA_S, LDA_S);
#pragma unroll
        for (int j = 0; j < 4; j++)
            wmma::load_matrix_sync(b[0][j], Bb + wn * 64 + j * 16, LDB_S);

#pragma unroll
        for (int kk = 0; kk < 4; kk++) {
            int cur = kk & 1, nxt = cur ^ 1;
            if (kk < 3) {   // issue next-kk fragment loads ahead of this kk's MMAs
#pragma unroll
                for (int i = 0; i < 4; i++)
                    wmma::load_matrix_sync(a[nxt][i], Ab + (wm * 64 + i * 16) * LDA_S + (kk + 1) * 16, LDA_S);
#pragma unroll
                for (int j = 0; j < 4; j++)
                    wmma::load_matrix_sync(b[nxt][j], Bb + (kk + 1) * 16 * LDB_S + wn * 64 + j * 16, LDB_S);
            }
#pragma unroll
            for (int i = 0; i < 4; i++)
#pragma unroll
                for (int j = 0; j < 4; j++)
                    wmma::mma_sync(c[i][j], a[cur][i], b[cur][j], c[i][j]);
        }
    }

    if (!relu_half) {
        // direct fp32 store, no bias (bias folded into combine)
#pragma unroll
        for (int i = 0; i < 4; i++)
#pragma unroll
            for (int j = 0; j < 4; j++) {
                float* o = (float*)Out + (size_t)(row0 + wm * 64 + i * 16) * N
                         + bn * BN + wn * 64 + j * 16;
                wmma::store_matrix_sync(o, c[i][j], N, wmma::mem_row_major);
            }
        return;
    }

    __syncthreads();   // protect smA before epilogue staging reuse
    float* cst = reinterpret_cast<float*>(smA) + warp * 256;
    int lr = lane >> 1, lc = (lane & 1) * 8;
#pragma unroll
    for (int i = 0; i < 4; i++)
#pragma unroll
        for (int j = 0; j < 4; j++) {
            wmma::store_matrix_sync(cst, c[i][j], 16, wmma::mem_row_major);
            __syncwarp();
            int gr = row0 + wm * 64 + i * 16 + lr;
            int gc = bn * BN + wn * 64 + j * 16 + lc;
            const float* srcp = cst + lr * 16 + lc;
            __half h[8];
#pragma unroll
            for (int u = 0; u < 8; u++) {
                float v = srcp[u] + bp_e[gc + u];
                h[u] = __float2half(v > 0.f ? v : 0.f);
            }
            *(uint4*)((__half*)Out + (size_t)gr * N + gc) = *(uint4*)h;
            __syncwarp();
        }
}

__global__ void k_combine(const float* __restrict__ b2, float* __restrict__ out) {
    int idx = blockIdx.x * blockDim.x + threadIdx.x;
    const int CW = D / 4;
    if (idx >= T * CW) return;
    int t = idx / CW, c4 = (idx % CW) * 4;
    int p0 = g_pos[2 * t], p1 = g_pos[2 * t + 1];
    int e0 = g_texp[2 * t], e1 = g_texp[2 * t + 1];
    float w0 = g_twt[2 * t], w1 = g_twt[2 * t + 1];
    float4 a = *(const float4*)(g_O + (size_t)p0 * D + c4);
    float4 b = *(const float4*)(g_O + (size_t)p1 * D + c4);
    float4 ba = *(const float4*)(b2 + (size_t)e0 * D + c4);
    float4 bb = *(const float4*)(b2 + (size_t)e1 * D + c4);
    float4 r;
    r.x = w0 * (a.x + ba.x) + w1 * (b.x + bb.x);
    r.y = w0 * (a.y + ba.y) + w1 * (b.y + bb.y);
    r.z = w0 * (a.z + ba.z) + w1 * (b.z + bb.z);
    r.w = w0 * (a.w + ba.w) + w1 * (b.w + bb.w);
    *(float4*)(out + (size_t)t * D + c4) = r;
}

extern "C" void kernel_launch(void* const* d_in, const int* in_sizes, int n_in,
                              void* d_out, int out_size) {
    const float* x  = (const float*)d_in[0];
    const float* Wg = (const float*)d_in[1];
    const float* bg = (const float*)d_in[2];
    const float* W1 = (const float*)d_in[3];
    const float* b1 = (const float*)d_in[4];
    const float* W2 = (const float*)d_in[5];
    const float* b2 = (const float*)d_in[6];
    float* out = (float*)d_out;

    __half *w1h, *w2h, *xh, *Hh; float* Oo; int* rowsp;
    cudaGetSymbolAddress((void**)&w1h, g_W1h);
    cudaGetSymbolAddress((void**)&w2h, g_W2h);
    cudaGetSymbolAddress((void**)&xh, g_xh);
    cudaGetSymbolAddress((void**)&Hh, g_H);
    cudaGetSymbolAddress((void**)&Oo, g_O);
    cudaGetSymbolAddress((void**)&rowsp, g_rows);

    cudaFuncSetAttribute(k_gemm, cudaFuncAttributeMaxDynamicSharedMemorySize, SMEM_DYN);
    cudaFuncSetAttribute(k_gemm, cudaFuncAttributePreferredSharedMemoryCarveout, 63);

    k_zero<<<1, 32>>>();
    k_gate<<<T / 8, 256>>>(x, Wg, bg);
    k_sched<<<1, 32>>>();
    k_scatter<<<T / 256, 256>>>();
    size_t nX = (size_t)T * D / 8;
    k_convW<<<(unsigned)((nX + 255) / 256), 256>>>(x, xh, nX);
    size_t nW = (size_t)E * D * F / 8;
    k_convW<<<(unsigned)((nW + 255) / 256), 256>>>(W1, w1h, nW);
    k_convW<<<(unsigned)((nW + 255) / 256), 256>>>(W2, w2h, nW);
    // GEMM1: H = relu(x[rows] @ W1[e] + b1[e])   [K=D, N=F], x=M-fast, .ca B
    k_gemm<<<dim3(MAXMT, F / BN), NTHR, SMEM_DYN>>>(xh, w1h, b1, (void*)Hh, D, F, 1, rowsp);
    // GEMM2: O = H @ W2[e]                        [K=F, N=D], x=M-fast, .ca B
    k_gemm<<<dim3(MAXMT, D / BN), NTHR, SMEM_DYN>>>(Hh, w2h, b2, (void*)Oo, F, D, 0, nullptr);
    k_combine<<<(T * (D / 4) + 255) / 256, 256>>>(b2, out);
}

// round 16
// speedup vs baseline: 1.0835x; 1.0386x over previous
#include <cuda_runtime.h>
#include <cuda_fp16.h>
#include <mma.h>
#include <cstdint>
#include <cstddef>
using namespace nvcuda;

#define DI __device__ __forceinline__

constexpr int D = 1024, F = 4096, E = 8, T = 8192;
constexpr int BM = 128, BN = 128, BK = 64;
constexpr int NST = 2;
constexpr int NTHR = 128;                  // 4 warps, 64x64 warp tiles (2x2)
constexpr int ROWS_PAD = 2 * T + E * BM;   // 17408
constexpr int MAXMT = ROWS_PAD / BM;       // 136
constexpr int LDA_S = BK + 8;              // 72 halfs
constexpr int LDB_S = BN + 8;              // 136 halfs
constexpr int A_ELE = BM * LDA_S;          // 9216 halfs / stage
constexpr int B_ELE = BK * LDB_S;          // 8704 halfs / stage
constexpr int SMEM_DYN = NST * (A_ELE + B_ELE) * 2;  // 71680 B (2 CTAs/SM, L1 ~85KB)

// ---- static device scratch (no allocations) ----
__device__ __half g_xh [(size_t)T * D];        // x fp16, token order (written by k_gate)
__device__ __half g_W1h[(size_t)E * D * F];
__device__ __half g_W2h[(size_t)E * F * D];
__device__ __half g_H  [(size_t)ROWS_PAD * F];
__device__ float  g_O  [(size_t)ROWS_PAD * D];
__device__ int   g_cnt[E], g_fill[E], g_off[E];
__device__ int   g_texp[2 * T];
__device__ float g_twt [2 * T];
__device__ int   g_pos [2 * T];
__device__ int   g_rows[ROWS_PAD];
__device__ int   g_tile_e[MAXMT], g_tile_r0[MAXMT];
__device__ int   g_nmt;

DI void cpa16_cg(void* dst, const void* src) {     // L1-bypass (A: no cross-CTA reuse)
    uint32_t d = (uint32_t)__cvta_generic_to_shared(dst);
    asm volatile("cp.async.cg.shared.global [%0], [%1], 16;"
                 :: "r"(d), "l"(__cvta_generic_to_global(src)) : "memory");
}
DI void cpa16_ca(void* dst, const void* src) {     // L1-allocating (B: shared by co-resident CTAs)
    uint32_t d = (uint32_t)__cvta_generic_to_shared(dst);
    asm volatile("cp.async.ca.shared.global [%0], [%1], 16;"
                 :: "r"(d), "l"(__cvta_generic_to_global(src)) : "memory");
}
#define CP_COMMIT asm volatile("cp.async.commit_group;" ::: "memory")
#define CP_WAIT(n) asm volatile("cp.async.wait_group %0;" :: "n"(n) : "memory")

// ---- gating: one warp per token (scalar coalesced loads) + fused x->fp16 ----
__global__ void k_zero() { if (threadIdx.x < E) { g_cnt[threadIdx.x] = 0; g_fill[threadIdx.x] = 0; } }

__global__ void k_gate(const float* __restrict__ x, const float* __restrict__ Wg,
                       const float* __restrict__ bg) {
    int warp = threadIdx.x >> 5, lane = threadIdx.x & 31;
    int t = blockIdx.x * 8 + warp;
    if (t >= T) return;
    float acc[E];
#pragma unroll
    for (int e = 0; e < E; e++) acc[e] = 0.f;
    const float* xr = x + (size_t)t * D;
    __half* xo = g_xh + (size_t)t * D;
    for (int d = lane; d < D; d += 32) {
        float xv = xr[d];
        xo[d] = __float2half(xv);                 // fused fp16 conversion
        const float4* w = (const float4*)(Wg + (size_t)d * E);
        float4 w0 = w[0], w1 = w[1];
        acc[0] += xv * w0.x; acc[1] += xv * w0.y; acc[2] += xv * w0.z; acc[3] += xv * w0.w;
        acc[4] += xv * w1.x; acc[5] += xv * w1.y; acc[6] += xv * w1.z; acc[7] += xv * w1.w;
    }
#pragma unroll
    for (int e = 0; e < E; e++)
#pragma unroll
        for (int o = 16; o > 0; o >>= 1) acc[e] += __shfl_down_sync(0xffffffffu, acc[e], o);
    if (lane == 0) {
        float l[E], m = -1e30f;
#pragma unroll
        for (int e = 0; e < E; e++) { l[e] = acc[e] + bg[e]; m = fmaxf(m, l[e]); }
        float p[E], s = 0.f;
#pragma unroll
        for (int e = 0; e < E; e++) { p[e] = __expf(l[e] - m); s += p[e]; }
        float inv = 1.f / s;
#pragma unroll
        for (int e = 0; e < E; e++) p[e] *= inv;
        int e0 = 0;
#pragma unroll
        for (int e = 1; e < E; e++) if (p[e] > p[e0]) e0 = e;
        int e1 = (e0 == 0) ? 1 : 0;
#pragma unroll
        for (int e = 0; e < E; e++) if (e != e0 && p[e] > p[e1]) e1 = e;
        g_texp[2 * t] = e0;     g_twt[2 * t] = p[e0];
        g_texp[2 * t + 1] = e1; g_twt[2 * t + 1] = p[e1];
        atomicAdd(&g_cnt[e0], 1); atomicAdd(&g_cnt[e1], 1);
    }
}

__global__ void k_sched() {
    if (threadIdx.x == 0) {
        int off = 0, nt = 0;
        for (int e = 0; e < E; e++) {
            g_off[e] = off;
            int c = g_cnt[e], ntile = (c + BM - 1) / BM;
            for (int i = 0; i < ntile; i++) { g_tile_e[nt] = e; g_tile_r0[nt] = off + i * BM; nt++; }
            off += ntile * BM;
        }
        g_nmt = nt;
    }
}

__global__ void k_scatter() {
    int t = blockIdx.x * blockDim.x + threadIdx.x;
    if (t >= T) return;
#pragma unroll
    for (int k = 0; k < 2; k++) {
        int e = g_texp[2 * t + k];
        int p = atomicAdd(&g_fill[e], 1);
        int row = g_off[e] + p;
        g_pos[2 * t + k] = row;
        g_rows[row] = t;
    }
}

__global__ void k_convW(const float* __restrict__ src, __half* __restrict__ dst, size_t n8) {
    size_t idx = (size_t)blockIdx.x * blockDim.x + threadIdx.x;
    if (idx >= n8) return;
    const float4* s = (const float4*)(src + idx * 8);
    float4 a = s[0], b = s[1];
    __half h[8];
    h[0] = __float2half(a.x); h[1] = __float2half(a.y); h[2] = __float2half(a.z); h[3] = __float2half(a.w);
    h[4] = __float2half(b.x); h[5] = __float2half(b.y); h[6] = __float2half(b.z); h[7] = __float2half(b.w);
    *(uint4*)(dst + idx * 8) = *(uint4*)h;
}

// ---- tiled wmma GEMM: 128x128 CTA, 4 warps @ 64x64, NST=2, 2 CTAs/SM ----
// Grid x=M-fast; B via .ca (co-resident CTAs, adjacent M-tiles same bn, share B in L1).
__global__ __launch_bounds__(NTHR, 2) void k_gemm(
    const __half* __restrict__ A, const __half* __restrict__ Bw,
    const float* __restrict__ bias, void* __restrict__ Out,
    int K, int N, int relu_half, const int* __restrict__ rmap)
{
    if (blockIdx.x >= g_nmt) return;
    int e = g_tile_e[blockIdx.x], row0 = g_tile_r0[blockIdx.x];
    int bn = blockIdx.y;
    const __half* Be = Bw + (size_t)e * K * N;
    const float* bp_e = bias + (size_t)e * N;

    extern __shared__ __align__(16) __half smem[];
    __half* smA = smem;
    __half* smB = smem + NST * A_ELE;
    __shared__ int srows[BM];

    int tid = threadIdx.x, lane = tid & 31, warp = tid >> 5;
    int wm = warp >> 1, wn = warp & 1;        // 2x2 warp grid, 64x64 each

    srows[tid] = rmap ? rmap[row0 + tid] : (row0 + tid);
    __syncthreads();

    wmma::fragment<wmma::accumulator, 16, 16, 16, float> c[4][4];
#pragma unroll
    for (int i = 0; i < 4; i++)
#pragma unroll
        for (int j = 0; j < 4; j++) wmma::fill_fragment(c[i][j], 0.f);

    auto load_tiles = [&](int buf, int k0) {
        __half* dA = smA + buf * A_ELE;
        __half* dB = smB + buf * B_ELE;
#pragma unroll
        for (int i = 0; i < 8; i++) {              // A: 128 rows x 8 chunks of 16B
            int q = i * NTHR + tid;
            int r = q >> 3, ch = q & 7;
            cpa16_cg(dA + r * LDA_S + ch * 8, A + (size_t)srows[r] * K + k0 + ch * 8);
        }
#pragma unroll
        for (int i = 0; i < 8; i++) {              // B: 64 rows x 16 chunks of 16B
            int q = i * NTHR + tid;
            int r = q >> 4, ch = q & 15;
            cpa16_ca(dB + r * LDB_S + ch * 8, Be + (size_t)(k0 + r) * N + bn * BN + ch * 8);
        }
    };

    int ktiles = K / BK;
    load_tiles(0, 0); CP_COMMIT;

    wmma::fragment<wmma::matrix_a, 16, 16, 16, half, wmma::row_major> a[2][4];
    wmma::fragment<wmma::matrix_b, 16, 16, 16, half, wmma::row_major> b[2][4];

    for (int kt = 0; kt < ktiles; kt++) {
        CP_WAIT(0);        // stage kt resident (loaded during compute of kt-1)
        __syncthreads();   // all warps done with buf (kt+1)&1 from compute kt-1
        if (kt + 1 < ktiles) { load_tiles((kt + 1) & 1, (kt + 1) * BK); CP_COMMIT; }

        const __half* Ab = smA + (kt & 1) * A_ELE;
        const __half* Bb = smB + (kt & 1) * B_ELE;

        // preload kk=0 fragments into slot 0
#pragma unroll
        for (int i = 0; i < 4; i++)
            wmma::load_matrix_sync(a[0][i], Ab + (wm * 64 + i * 16) * LDA_S, LDA_S);
#pragma unroll
        for (int j = 0; j < 4; j++)
            wmma::load_matrix_sync(b[0][j], Bb + wn * 64 + j * 16, LDB_S);

#pragma unroll
        for (int kk = 0; kk < 4; kk++) {
            int cur = kk & 1, nxt = cur ^ 1;
            if (kk < 3) {   // issue next-kk fragment loads ahead of this kk's MMAs
#pragma unroll
                for (int i = 0; i < 4; i++)
                    wmma::load_matrix_sync(a[nxt][i], Ab + (wm * 64 + i * 16) * LDA_S + (kk + 1) * 16, LDA_S);
#pragma unroll
                for (int j = 0; j < 4; j++)
                    wmma::load_matrix_sync(b[nxt][j], Bb + (kk + 1) * 16 * LDB_S + wn * 64 + j * 16, LDB_S);
            }
#pragma unroll
            for (int i = 0; i < 4; i++)
#pragma unroll
                for (int j = 0; j < 4; j++)
                    wmma::mma_sync(c[i][j], a[cur][i], b[cur][j], c[i][j]);
        }
    }

    if (!relu_half) {
        // direct fp32 store, no bias (bias folded into combine)
#pragma unroll
        for (int i = 0; i < 4; i++)
#pragma unroll
            for (int j = 0; j < 4; j++) {
                float* o = (float*)Out + (size_t)(row0 + wm * 64 + i * 16) * N
                         + bn * BN + wn * 64 + j * 16;
                wmma::store_matrix_sync(o, c[i][j], N, wmma::mem_row_major);
            }
        return;
    }

    __syncthreads();   // protect smA before epilogue staging reuse
    float* cst = reinterpret_cast<float*>(smA) + warp * 256;
    int lr = lane >> 1, lc = (lane & 1) * 8;
#pragma unroll
    for (int i = 0; i < 4; i++)
#pragma unroll
        for (int j = 0; j < 4; j++) {
            wmma::store_matrix_sync(cst, c[i][j], 16, wmma::mem_row_major);
            __syncwarp();
            int gr = row0 + wm * 64 + i * 16 + lr;
            int gc = bn * BN + wn * 64 + j * 16 + lc;
            const float* srcp = cst + lr * 16 + lc;
            __half h[8];
#pragma unroll
            for (int u = 0; u < 8; u++) {
                float v = srcp[u] + bp_e[gc + u];
                h[u] = __float2half(v > 0.f ? v : 0.f);
            }
            *(uint4*)((__half*)Out + (size_t)gr * N + gc) = *(uint4*)h;
            __syncwarp();
        }
}

__global__ void k_combine(const float* __restrict__ b2, float* __restrict__ out) {
    int idx = blockIdx.x * blockDim.x + threadIdx.x;
    const int CW = D / 4;
    if (idx >= T * CW) return;
    int t = idx / CW, c4 = (idx % CW) * 4;
    int p0 = g_pos[2 * t], p1 = g_pos[2 * t + 1];
    int e0 = g_texp[2 * t], e1 = g_texp[2 * t + 1];
    float w0 = g_twt[2 * t], w1 = g_twt[2 * t + 1];
    float4 a = *(const float4*)(g_O + (size_t)p0 * D + c4);
    float4 b = *(const float4*)(g_O + (size_t)p1 * D + c4);
    float4 ba = *(const float4*)(b2 + (size_t)e0 * D + c4);
    float4 bb = *(const float4*)(b2 + (size_t)e1 * D + c4);
    float4 r;
    r.x = w0 * (a.x + ba.x) + w1 * (b.x + bb.x);
    r.y = w0 * (a.y + ba.y) + w1 * (b.y + bb.y);
    r.z = w0 * (a.z + ba.z) + w1 * (b.z + bb.z);
    r.w = w0 * (a.w + ba.w) + w1 * (b.w + bb.w);
    *(float4*)(out + (size_t)t * D + c4) = r;
}

extern "C" void kernel_launch(void* const* d_in, const int* in_sizes, int n_in,
                              void* d_out, int out_size) {
    const float* x  = (const float*)d_in[0];
    const float* Wg = (const float*)d_in[1];
    const float* bg = (const float*)d_in[2];
    const float* W1 = (const float*)d_in[3];
    const float* b1 = (const float*)d_in[4];
    const float* W2 = (const float*)d_in[5];
    const float* b2 = (const float*)d_in[6];
    float* out = (float*)d_out;

    __half *w1h, *w2h, *xh, *Hh; float* Oo; int* rowsp;
    cudaGetSymbolAddress((void**)&w1h, g_W1h);
    cudaGetSymbolAddress((void**)&w2h, g_W2h);
    cudaGetSymbolAddress((void**)&xh, g_xh);
    cudaGetSymbolAddress((void**)&Hh, g_H);
    cudaGetSymbolAddress((void**)&Oo, g_O);
    cudaGetSymbolAddress((void**)&rowsp, g_rows);

    cudaFuncSetAttribute(k_gemm, cudaFuncAttributeMaxDynamicSharedMemorySize, SMEM_DYN);
    cudaFuncSetAttribute(k_gemm, cudaFuncAttributePreferredSharedMemoryCarveout, 63);

    k_zero<<<1, 32>>>();
    k_gate<<<T / 8, 256>>>(x, Wg, bg);           // also writes g_xh (fused x->fp16)
    k_sched<<<1, 32>>>();
    k_scatter<<<T / 256, 256>>>();
    size_t nW = (size_t)E * D * F / 8;
    k_convW<<<(unsigned)((nW + 255) / 256), 256>>>(W1, w1h, nW);
    k_convW<<<(unsigned)((nW + 255) / 256), 256>>>(W2, w2h, nW);
    // GEMM1: H = relu(x[rows] @ W1[e] + b1[e])   [K=D, N=F], x=M-fast, .ca B
    k_gemm<<<dim3(MAXMT, F / BN), NTHR, SMEM_DYN>>>(xh, w1h, b1, (void*)Hh, D, F, 1, rowsp);
    // GEMM2: O = H @ W2[e]                        [K=F, N=D], x=M-fast, .ca B
    k_gemm<<<dim3(MAXMT, D / BN), NTHR, SMEM_DYN>>>(Hh, w2h, b2, (void*)Oo, F, D, 0, nullptr);
    k_combine<<<(T * (D / 4) + 255) / 256, 256>>>(b2, out);
}

// round 17
// speedup vs baseline: 1.0976x; 1.0131x over previous
#include <cuda_runtime.h>
#include <cuda_fp16.h>
#include <mma.h>
#include <cstdint>
#include <cstddef>
using namespace nvcuda;

#define DI __device__ __forceinline__

constexpr int D = 1024, F = 4096, E = 8, T = 8192;
constexpr int BM = 128, BN = 128, BK = 64;
constexpr int NST = 2;
constexpr int NTHR = 128;                  // 4 warps, 64x64 warp tiles (2x2)
constexpr int ROWS_PAD = 2 * T + E * BM;   // 17408
constexpr int MAXMT = ROWS_PAD / BM;       // 136
constexpr int LDA_S = BK + 8;              // 72 halfs
constexpr int LDB_S = BN + 8;              // 136 halfs
constexpr int A_ELE = BM * LDA_S;          // 9216 halfs / stage
constexpr int B_ELE = BK * LDB_S;          // 8704 halfs / stage
constexpr int SMEM_DYN = NST * (A_ELE + B_ELE) * 2;  // 71680 B (2 CTAs/SM, L1 ~85KB)

// conversion sizes (in float8-groups)
constexpr size_t N8_W = (size_t)E * D * F / 8;   // per weight tensor
constexpr size_t N8_X = (size_t)T * D / 8;       // x
constexpr size_t N8_ALL = 2 * N8_W + N8_X;

// ---- static device scratch (no allocations) ----
__device__ __half g_xh [(size_t)T * D];        // x fp16, token order
__device__ __half g_W1h[(size_t)E * D * F];
__device__ __half g_W2h[(size_t)E * F * D];
__device__ __half g_H  [(size_t)ROWS_PAD * F];
__device__ float  g_O  [(size_t)ROWS_PAD * D];
__device__ int   g_cnt[E], g_fill[E], g_off[E];
__device__ int   g_texp[2 * T];
__device__ float g_twt [2 * T];
__device__ int   g_pos [2 * T];
__device__ int   g_rows[ROWS_PAD];
__device__ int   g_tile_e[MAXMT], g_tile_r0[MAXMT];
__device__ int   g_nmt;

DI void cpa16_cg(void* dst, const void* src) {     // L1-bypass (A: no cross-CTA reuse)
    uint32_t d = (uint32_t)__cvta_generic_to_shared(dst);
    asm volatile("cp.async.cg.shared.global [%0], [%1], 16;"
                 :: "r"(d), "l"(__cvta_generic_to_global(src)) : "memory");
}
DI void cpa16_ca(void* dst, const void* src) {     // L1-allocating (B: shared by co-resident CTAs)
    uint32_t d = (uint32_t)__cvta_generic_to_shared(dst);
    asm volatile("cp.async.ca.shared.global [%0], [%1], 16;"
                 :: "r"(d), "l"(__cvta_generic_to_global(src)) : "memory");
}
#define CP_COMMIT asm volatile("cp.async.commit_group;" ::: "memory")
#define CP_WAIT(n) asm volatile("cp.async.wait_group %0;" :: "n"(n) : "memory")

// ---- gating: one warp per token (scalar coalesced loads; R13 champion form) ----
__global__ void k_zero() { if (threadIdx.x < E) { g_cnt[threadIdx.x] = 0; g_fill[threadIdx.x] = 0; } }

__global__ void k_gate(const float* __restrict__ x, const float* __restrict__ Wg,
                       const float* __restrict__ bg) {
    int warp = threadIdx.x >> 5, lane = threadIdx.x & 31;
    int t = blockIdx.x * 8 + warp;
    if (t >= T) return;
    float acc[E];
#pragma unroll
    for (int e = 0; e < E; e++) acc[e] = 0.f;
    const float* xr = x + (size_t)t * D;
    for (int d = lane; d < D; d += 32) {
        float xv = xr[d];
        const float4* w = (const float4*)(Wg + (size_t)d * E);
        float4 w0 = w[0], w1 = w[1];
        acc[0] += xv * w0.x; acc[1] += xv * w0.y; acc[2] += xv * w0.z; acc[3] += xv * w0.w;
        acc[4] += xv * w1.x; acc[5] += xv * w1.y; acc[6] += xv * w1.z; acc[7] += xv * w1.w;
    }
#pragma unroll
    for (int e = 0; e < E; e++)
#pragma unroll
        for (int o = 16; o > 0; o >>= 1) acc[e] += __shfl_down_sync(0xffffffffu, acc[e], o);
    if (lane == 0) {
        float l[E], m = -1e30f;
#pragma unroll
        for (int e = 0; e < E; e++) { l[e] = acc[e] + bg[e]; m = fmaxf(m, l[e]); }
        float p[E], s = 0.f;
#pragma unroll
        for (int e = 0; e < E; e++) { p[e] = __expf(l[e] - m); s += p[e]; }
        float inv = 1.f / s;
#pragma unroll
        for (int e = 0; e < E; e++) p[e] *= inv;
        int e0 = 0;
#pragma unroll
        for (int e = 1; e < E; e++) if (p[e] > p[e0]) e0 = e;
        int e1 = (e0 == 0) ? 1 : 0;
#pragma unroll
        for (int e = 0; e < E; e++) if (e != e0 && p[e] > p[e1]) e1 = e;
        g_texp[2 * t] = e0;     g_twt[2 * t] = p[e0];
        g_texp[2 * t + 1] = e1; g_twt[2 * t + 1] = p[e1];
        atomicAdd(&g_cnt[e0], 1); atomicAdd(&g_cnt[e1], 1);
    }
}

__global__ void k_sched() {
    if (threadIdx.x == 0) {
        int off = 0, nt = 0;
        for (int e = 0; e < E; e++) {
            g_off[e] = off;
            int c = g_cnt[e], ntile = (c + BM - 1) / BM;
            for (int i = 0; i < ntile; i++) { g_tile_e[nt] = e; g_tile_r0[nt] = off + i * BM; nt++; }
            off += ntile * BM;
        }
        g_nmt = nt;
    }
}

__global__ void k_scatter() {
    int t = blockIdx.x * blockDim.x + threadIdx.x;
    if (t >= T) return;
#pragma unroll
    for (int k = 0; k < 2; k++) {
        int e = g_texp[2 * t + k];
        int p = atomicAdd(&g_fill[e], 1);
        int row = g_off[e] + p;
        g_pos[2 * t + k] = row;
        g_rows[row] = t;
    }
}

// single merged fp32->fp16 conversion pass: [W1 | W2 | x]
__global__ void k_convAll(const float* __restrict__ W1, const float* __restrict__ W2,
                          const float* __restrict__ x) {
    size_t idx = (size_t)blockIdx.x * blockDim.x + threadIdx.x;
    if (idx >= N8_ALL) return;
    const float* src;
    __half* dst;
    size_t off;
    if (idx < N8_W)            { src = W1; dst = g_W1h; off = idx; }
    else if (idx < 2 * N8_W)   { src = W2; dst = g_W2h; off = idx - N8_W; }
    else                       { src = x;  dst = g_xh;  off = idx - 2 * N8_W; }
    const float4* s = (const float4*)(src + off * 8);
    float4 a = s[0], b = s[1];
    __half h[8];
    h[0] = __float2half(a.x); h[1] = __float2half(a.y); h[2] = __float2half(a.z); h[3] = __float2half(a.w);
    h[4] = __float2half(b.x); h[5] = __float2half(b.y); h[6] = __float2half(b.z); h[7] = __float2half(b.w);
    *(uint4*)(dst + off * 8) = *(uint4*)h;
}

// ---- tiled wmma GEMM: 128x128 CTA, 4 warps @ 64x64, NST=2, 2 CTAs/SM ----
// Grid x=M-fast; B via .ca (co-resident CTAs, adjacent M-tiles same bn, share B in L1).
__global__ __launch_bounds__(NTHR, 2) void k_gemm(
    const __half* __restrict__ A, const __half* __restrict__ Bw,
    const float* __restrict__ bias, void* __restrict__ Out,
    int K, int N, int relu_half, const int* __restrict__ rmap)
{
    if (blockIdx.x >= g_nmt) return;
    int e = g_tile_e[blockIdx.x], row0 = g_tile_r0[blockIdx.x];
    int bn = blockIdx.y;
    const __half* Be = Bw + (size_t)e * K * N;
    const float* bp_e = bias + (size_t)e * N;

    extern __shared__ __align__(16) __half smem[];
    __half* smA = smem;
    __half* smB = smem + NST * A_ELE;
    __shared__ int srows[BM];

    int tid = threadIdx.x, lane = tid & 31, warp = tid >> 5;
    int wm = warp >> 1, wn = warp & 1;        // 2x2 warp grid, 64x64 each

    srows[tid] = rmap ? rmap[row0 + tid] : (row0 + tid);
    __syncthreads();

    wmma::fragment<wmma::accumulator, 16, 16, 16, float> c[4][4];
#pragma unroll
    for (int i = 0; i < 4; i++)
#pragma unroll
        for (int j = 0; j < 4; j++) wmma::fill_fragment(c[i][j], 0.f);

    auto load_tiles = [&](int buf, int k0) {
        __half* dA = smA + buf * A_ELE;
        __half* dB = smB + buf * B_ELE;
#pragma unroll
        for (int i = 0; i < 8; i++) {              // A: 128 rows x 8 chunks of 16B
            int q = i * NTHR + tid;
            int r = q >> 3, ch = q & 7;
            cpa16_cg(dA + r * LDA_S + ch * 8, A + (size_t)srows[r] * K + k0 + ch * 8);
        }
#pragma unroll
        for (int i = 0; i < 8; i++) {              // B: 64 rows x 16 chunks of 16B
            int q = i * NTHR + tid;
            int r = q >> 4, ch = q & 15;
            cpa16_ca(dB + r * LDB_S + ch * 8, Be + (size_t)(k0 + r) * N + bn * BN + ch * 8);
        }
    };

    int ktiles = K / BK;
    load_tiles(0, 0); CP_COMMIT;

    wmma::fragment<wmma::matrix_a, 16, 16, 16, half, wmma::row_major> a[2][4];
    wmma::fragment<wmma::matrix_b, 16, 16, 16, half, wmma::row_major> b[2][4];

    for (int kt = 0; kt < ktiles; kt++) {
        CP_WAIT(0);        // stage kt resident (loaded during compute of kt-1)
        __syncthreads();   // all warps done with buf (kt+1)&1 from compute kt-1
        if (kt + 1 < ktiles) { load_tiles((kt + 1) & 1, (kt + 1) * BK); CP_COMMIT; }

        const __half* Ab = smA + (kt & 1) * A_ELE;
        const __half* Bb = smB + (kt & 1) * B_ELE;

        // preload kk=0 fragments into slot 0
#pragma unroll
        for (int i = 0; i < 4; i++)
            wmma::load_matrix_sync(a[0][i], Ab + (wm * 64 + i * 16) * LDA_S, LDA_S);
#pragma unroll
        for (int j = 0; j < 4; j++)
            wmma::load_matrix_sync(b[0][j], Bb + wn * 64 + j * 16, LDB_S);

#pragma unroll
        for (int kk = 0; kk < 4; kk++) {
            int cur = kk & 1, nxt = cur ^ 1;
            if (kk < 3) {   // issue next-kk fragment loads ahead of this kk's MMAs
#pragma unroll
                for (int i = 0; i < 4; i++)
                    wmma::load_matrix_sync(a[nxt][i], Ab + (wm * 64 + i * 16) * LDA_S + (kk + 1) * 16, LDA_S);
#pragma unroll
                for (int j = 0; j < 4; j++)
                    wmma::load_matrix_sync(b[nxt][j], Bb + (kk + 1) * 16 * LDB_S + wn * 64 + j * 16, LDB_S);
            }
#pragma unroll
            for (int i = 0; i < 4; i++)
#pragma unroll
                for (int j = 0; j < 4; j++)
                    wmma::mma_sync(c[i][j], a[cur][i], b[cur][j], c[i][j]);
        }
    }

    if (!relu_half) {
        // direct fp32 store, no bias (bias folded into combine)
#pragma unroll
        for (int i = 0; i < 4; i++)
#pragma unroll
            for (int j = 0; j < 4; j++) {
                float* o = (float*)Out + (size_t)(row0 + wm * 64 + i * 16) * N
                         + bn * BN + wn * 64 + j * 16;
                wmma::store_matrix_sync(o, c[i][j], N, wmma::mem_row_major);
            }
        return;
    }

    __syncthreads();   // protect smA before epilogue staging reuse
    float* cst = reinterpret_cast<float*>(smA) + warp * 256;
    int lr = lane >> 1, lc = (lane & 1) * 8;
#pragma unroll
    for (int i = 0; i < 4; i++)
#pragma unroll
        for (int j = 0; j < 4; j++) {
            wmma::store_matrix_sync(cst, c[i][j], 16, wmma::mem_row_major);
            __syncwarp();
            int gr = row0 + wm * 64 + i * 16 + lr;
            int gc = bn * BN + wn * 64 + j * 16 + lc;
            const float* srcp = cst + lr * 16 + lc;
            __half h[8];
#pragma unroll
            for (int u = 0; u < 8; u++) {
                float v = srcp[u] + bp_e[gc + u];
                h[u] = __float2half(v > 0.f ? v : 0.f);
            }
            *(uint4*)((__half*)Out + (size_t)gr * N + gc) = *(uint4*)h;
            __syncwarp();
        }
}

__global__ void k_combine(const float* __restrict__ b2, float* __restrict__ out) {
    int idx = blockIdx.x * blockDim.x + threadIdx.x;
    const int CW = D / 4;
    if (idx >= T * CW) return;
    int t = idx / CW, c4 = (idx % CW) * 4;
    int p0 = g_pos[2 * t], p1 = g_pos[2 * t + 1];
    int e0 = g_texp[2 * t], e1 = g_texp[2 * t + 1];
    float w0 = g_twt[2 * t], w1 = g_twt[2 * t + 1];
    float4 a = *(const float4*)(g_O + (size_t)p0 * D + c4);
    float4 b = *(const float4*)(g_O + (size_t)p1 * D + c4);
    float4 ba = *(const float4*)(b2 + (size_t)e0 * D + c4);
    float4 bb = *(const float4*)(b2 + (size_t)e1 * D + c4);
    float4 r;
    r.x = w0 * (a.x + ba.x) + w1 * (b.x + bb.x);
    r.y = w0 * (a.y + ba.y) + w1 * (b.y + bb.y);
    r.z = w0 * (a.z + ba.z) + w1 * (b.z + bb.z);
    r.w = w0 * (a.w + ba.w) + w1 * (b.w + bb.w);
    *(float4*)(out + (size_t)t * D + c4) = r;
}

extern "C" void kernel_launch(void* const* d_in, const int* in_sizes, int n_in,
                              void* d_out, int out_size) {
    const float* x  = (const float*)d_in[0];
    const float* Wg = (const float*)d_in[1];
    const float* bg = (const float*)d_in[2];
    const float* W1 = (const float*)d_in[3];
    const float* b1 = (const float*)d_in[4];
    const float* W2 = (const float*)d_in[5];
    const float* b2 = (const float*)d_in[6];
    float* out = (float*)d_out;

    __half *w1h, *w2h, *xh, *Hh; float* Oo; int* rowsp;
    cudaGetSymbolAddress((void**)&w1h, g_W1h);
    cudaGetSymbolAddress((void**)&w2h, g_W2h);
    cudaGetSymbolAddress((void**)&xh, g_xh);
    cudaGetSymbolAddress((void**)&Hh, g_H);
    cudaGetSymbolAddress((void**)&Oo, g_O);
    cudaGetSymbolAddress((void**)&rowsp, g_rows);

    cudaFuncSetAttribute(k_gemm, cudaFuncAttributeMaxDynamicSharedMemorySize, SMEM_DYN);
    cudaFuncSetAttribute(k_gemm, cudaFuncAttributePreferredSharedMemoryCarveout, 63);

    k_zero<<<1, 32>>>();
    k_gate<<<T / 8, 256>>>(x, Wg, bg);
    k_sched<<<1, 32>>>();
    k_scatter<<<T / 256, 256>>>();
    k_convAll<<<(unsigned)((N8_ALL + 255) / 256), 256>>>(W1, W2, x);
    // GEMM1: H = relu(x[rows] @ W1[e] + b1[e])   [K=D, N=F], x=M-fast, .ca B
    k_gemm<<<dim3(MAXMT, F / BN), NTHR, SMEM_DYN>>>(xh, w1h, b1, (void*)Hh, D, F, 1, rowsp);
    // GEMM2: O = H @ W2[e]                        [K=F, N=D], x=M-fast, .ca B
    k_gemm<<<dim3(MAXMT, D / BN), NTHR, SMEM_DYN>>>(Hh, w2h, b2, (void*)Oo, F, D, 0, nullptr);
    k_combine<<<(T * (D / 4) + 255) / 256, 256>>>(b2, out);
}